// round 1
// baseline (speedup 1.0000x reference)
#include <cuda_runtime.h>
#include <cstdint>
#include <cstddef>

#define Hc    256
#define CC    50
#define GG    512
#define NACT  200000
#define NRES  20000
#define NTIME 100000
#define EE    400000

// ---------------- scratch layout (floats) ----------------
static constexpr size_t OFF_A    = 0;                         // 200000*256
static constexpr size_t OFF_R    = 51200000;                  // 20000*256
static constexpr size_t OFF_T    = 56320000;                  // 100000*256
static constexpr size_t OFF_XA   = 81920000;                  // 200000*1024
static constexpr size_t OFF_XR   = 286720000;                 // 20000*512
static constexpr size_t OFF_XT   = 296960000;                 // 100000*512
static constexpr size_t OFF_INV  = 348160000;                 // 720000 (f,ra,ta,ar,at)
static constexpr size_t OFF_WF   = 348880000;                 // 2*8*65536 folded weights
static constexpr size_t OFF_BF   = 349928576;                 // 2*3*256 folded biases
static constexpr size_t OFF_LAST = 349930112;                 // 512 ints
static constexpr size_t TOTALF   = 349931008;

__device__ float g_buf[TOTALF];

// ---------------- small helpers ----------------
__device__ __forceinline__ void red_add_v4(float* a, float4 v) {
    asm volatile("red.global.add.v4.f32 [%0], {%1,%2,%3,%4};"
                 :: "l"(a), "f"(v.x), "f"(v.y), "f"(v.z), "f"(v.w) : "memory");
}

// out[i,j] = sum_k (A1+A2+A3)[i,k] * B[k,j]      (all 256x256, row-major)
__global__ void fold_w(const float* __restrict__ A1, const float* __restrict__ A2,
                       const float* __restrict__ A3, const float* __restrict__ B,
                       float* __restrict__ out) {
    int i = blockIdx.x, j = threadIdx.x;
    float acc = 0.f;
    for (int k = 0; k < Hc; k++) {
        float a = A1[i * Hc + k];
        if (A2) a += A2[i * Hc + k];
        if (A3) a += A3[i * Hc + k];
        acc = fmaf(a, B[k * Hc + j], acc);
    }
    out[i * Hc + j] = acc;
}

// out[j] = sum_k (b1+b2+b3)[k]*B[k,j] + blin[j]
__global__ void fold_b(const float* __restrict__ b1, const float* __restrict__ b2,
                       const float* __restrict__ b3, const float* __restrict__ B,
                       const float* __restrict__ blin, float* __restrict__ out) {
    int j = threadIdx.x;
    float acc = blin[j];
    for (int k = 0; k < Hc; k++) {
        float bb = b1[k];
        if (b2) bb += b2[k];
        if (b3) bb += b3[k];
        acc = fmaf(bb, B[k * Hc + j], acc);
    }
    out[j] = acc;
}

__global__ void count_k(const int* __restrict__ dst, float* __restrict__ cnt, int E) {
    int i = blockIdx.x * blockDim.x + threadIdx.x;
    if (i < E) atomicAdd(&cnt[dst[i]], 1.f);
}

__global__ void inv_k(float* __restrict__ p, int n) {
    int i = blockIdx.x * blockDim.x + threadIdx.x;
    if (i < n) { float c = p[i]; p[i] = 1.f / (c < 1.f ? 1.f : c); }
}

// one edge handled by 64 threads; 4 floats each via vector atomic
__global__ void scatter_k(const int* __restrict__ src, const int* __restrict__ dst,
                          const float* __restrict__ x, float* __restrict__ X,
                          int ldX, int sec, int E) {
    int t = blockIdx.x * blockDim.x + threadIdx.x;
    int e = t >> 6, lane = t & 63;
    if (e >= E) return;
    int s = __ldg(&src[e]), d = __ldg(&dst[e]);
    float4 v = *reinterpret_cast<const float4*>(x + (size_t)s * Hc + lane * 4);
    red_add_v4(X + (size_t)d * ldX + sec + lane * 4, v);
}

// Xa: scale 3 mean sections by inv degree, copy a into section 3
__global__ void finalize_act_k(float* __restrict__ Xa, const float* __restrict__ a,
                               const float* __restrict__ invf, const float* __restrict__ invra,
                               const float* __restrict__ invta) {
    size_t t = (size_t)blockIdx.x * blockDim.x + threadIdx.x;
    int node = (int)(t >> 8), q = (int)(t & 255);
    if (node >= NACT) return;
    float4* row = reinterpret_cast<float4*>(Xa + (size_t)node * 1024);
    if (q < 192) {
        float s = (q < 64) ? invf[node] : (q < 128 ? invra[node] : invta[node]);
        float4 v = row[q];
        v.x *= s; v.y *= s; v.z *= s; v.w *= s;
        row[q] = v;
    } else {
        row[q] = reinterpret_cast<const float4*>(a + (size_t)node * Hc)[q - 192];
    }
}

__global__ void finalize2_k(float* __restrict__ X, const float* __restrict__ xd,
                            const float* __restrict__ inv, int N) {
    size_t t = (size_t)blockIdx.x * blockDim.x + threadIdx.x;
    int node = (int)(t >> 7), q = (int)(t & 127);
    if (node >= N) return;
    float4* row = reinterpret_cast<float4*>(X + (size_t)node * 512);
    if (q < 64) {
        float s = inv[node];
        float4 v = row[q];
        v.x *= s; v.y *= s; v.z *= s; v.w *= s;
        row[q] = v;
    } else {
        row[q] = reinterpret_cast<const float4*>(xd + (size_t)node * Hc)[q - 64];
    }
}

__global__ void last_k(const int* __restrict__ batch, int* __restrict__ last, int N) {
    int i = blockIdx.x * blockDim.x + threadIdx.x;
    if (i < N) {
        if (i == N - 1 || batch[i + 1] != batch[i]) last[batch[i]] = i;
    }
}

// C[N,256] = relu?(A[N,K] @ W[K,256] + bias).  K multiple of 16.
// 64x256 block tile, 8x8 per-thread register tile, 256 threads.
__global__ void __launch_bounds__(256) gemm256(
        const float* __restrict__ A, const float* __restrict__ W,
        const float* __restrict__ bias, float* __restrict__ C,
        int N, int K, int relu) {
    __shared__ float As[16][68];
    __shared__ float Bs[16][256];
    const int tid = threadIdx.x;
    const int row0 = blockIdx.x * 64;
    const int ty = tid >> 5;            // 0..7  (rows ty*8 .. +7)
    const int tx = tid & 31;            // 0..31 (cols tx*8 .. +7)
    const int ar = tid >> 2;            // 0..63
    const int ac = (tid & 3) << 2;      // 0,4,8,12
    const int br = tid >> 4;            // 0..15
    const int bc = (tid & 15) << 4;     // 0..240

    float acc[8][8];
#pragma unroll
    for (int i = 0; i < 8; i++)
#pragma unroll
        for (int j = 0; j < 8; j++) acc[i][j] = 0.f;

    for (int k0 = 0; k0 < K; k0 += 16) {
        int gr = row0 + ar;
        float4 av = make_float4(0.f, 0.f, 0.f, 0.f);
        if (gr < N) av = *reinterpret_cast<const float4*>(A + (size_t)gr * K + k0 + ac);
        As[ac + 0][ar] = av.x; As[ac + 1][ar] = av.y;
        As[ac + 2][ar] = av.z; As[ac + 3][ar] = av.w;
#pragma unroll
        for (int q = 0; q < 4; q++) {
            *reinterpret_cast<float4*>(&Bs[br][bc + q * 4]) =
                *reinterpret_cast<const float4*>(W + (size_t)(k0 + br) * 256 + bc + q * 4);
        }
        __syncthreads();
#pragma unroll
        for (int k = 0; k < 16; k++) {
            float rA[8], rB[8];
#pragma unroll
            for (int i = 0; i < 8; i++) rA[i] = As[k][ty * 8 + i];
#pragma unroll
            for (int j = 0; j < 8; j++) rB[j] = Bs[k][tx * 8 + j];
#pragma unroll
            for (int i = 0; i < 8; i++)
#pragma unroll
                for (int j = 0; j < 8; j++)
                    acc[i][j] = fmaf(rA[i], rB[j], acc[i][j]);
        }
        __syncthreads();
    }
#pragma unroll
    for (int i = 0; i < 8; i++) {
        int gr = row0 + ty * 8 + i;
        if (gr >= N) continue;
#pragma unroll
        for (int jq = 0; jq < 2; jq++) {
            int col = tx * 8 + jq * 4;
            float4 v = make_float4(acc[i][jq * 4 + 0], acc[i][jq * 4 + 1],
                                   acc[i][jq * 4 + 2], acc[i][jq * 4 + 3]);
            if (bias) {
                v.x += bias[col]; v.y += bias[col + 1];
                v.z += bias[col + 2]; v.w += bias[col + 3];
            }
            if (relu) {
                v.x = fmaxf(v.x, 0.f); v.y = fmaxf(v.y, 0.f);
                v.z = fmaxf(v.z, 0.f); v.w = fmaxf(v.w, 0.f);
            }
            *reinterpret_cast<float4*>(C + (size_t)gr * 256 + col) = v;
        }
    }
}

// output heads: one block per graph
__global__ void heads_k(const float* __restrict__ a, const int* __restrict__ last,
                        const float* __restrict__ Wo, const float* __restrict__ bo,
                        const float* __restrict__ Wt, const float* __restrict__ bt,
                        const float* __restrict__ Wrm, const float* __restrict__ brm,
                        float* __restrict__ out) {
    int g = blockIdx.x;
    __shared__ float p[Hc];
    const float* row = a + (size_t)last[g] * Hc;
    for (int k = threadIdx.x; k < Hc; k += blockDim.x) p[k] = row[k];
    __syncthreads();
    int j = threadIdx.x;
    if (j < CC) {
        float acc = bo[j];
        for (int k = 0; k < Hc; k++) acc = fmaf(p[k], Wo[k * CC + j], acc);
        out[g * CC + j] = acc;
    } else if (j == CC) {
        float acc = bt[0];
        for (int k = 0; k < Hc; k++) acc = fmaf(p[k], Wt[k], acc);
        out[GG * CC + g] = acc;
    } else if (j == CC + 1) {
        float acc = brm[0];
        for (int k = 0; k < Hc; k++) acc = fmaf(p[k], Wrm[k], acc);
        out[GG * CC + GG + g] = acc;
    }
}

// ---------------- host orchestration ----------------
extern "C" void kernel_launch(void* const* d_in, const int* in_sizes, int n_in,
                              void* d_out, int out_size) {
    float* buf = nullptr;
    cudaGetSymbolAddress((void**)&buf, g_buf);

    float* A   = buf + OFF_A;
    float* R   = buf + OFF_R;
    float* T   = buf + OFF_T;
    float* XA  = buf + OFF_XA;
    float* XR  = buf + OFF_XR;
    float* XT  = buf + OFF_XT;
    float* INV = buf + OFF_INV;   // f@0, ra@200000, ta@400000, ar@600000, at@620000
    float* WF  = buf + OFF_WF;
    float* BF  = buf + OFF_BF;
    int*   LAST = reinterpret_cast<int*>(buf + OFF_LAST);

    const float* x_act  = (const float*)d_in[0];
    const float* x_res  = (const float*)d_in[1];
    const float* x_time = (const float*)d_in[2];
    const int* src_f  = (const int*)d_in[3];
    const int* dst_f  = (const int*)d_in[4];
    const int* src_ar = (const int*)d_in[5];
    const int* dst_ar = (const int*)d_in[6];
    const int* src_ra = (const int*)d_in[7];
    const int* dst_ra = (const int*)d_in[8];
    const int* src_at = (const int*)d_in[9];
    const int* dst_at = (const int*)d_in[10];
    const int* src_ta = (const int*)d_in[11];
    const int* dst_ta = (const int*)d_in[12];
    const int* batch  = (const int*)d_in[13];

    // num_graphs may or may not be materialized as an input
    int w = (in_sizes[14] <= 4) ? 15 : 14;
    const float* Wp_act = (const float*)d_in[w + 0];
    const float* Wp_res = (const float*)d_in[w + 1];
    const float* Wp_tim = (const float*)d_in[w + 2];
    const float* Wl     = (const float*)d_in[w + 3];
    const float* bl     = (const float*)d_in[w + 4];
    const float* Wr     = (const float*)d_in[w + 5];
    const float* Wlin   = (const float*)d_in[w + 6];
    const float* blin   = (const float*)d_in[w + 7];
    const float* Wo     = (const float*)d_in[w + 8];
    const float* bo     = (const float*)d_in[w + 9];
    const float* Wt     = (const float*)d_in[w + 10];
    const float* bt     = (const float*)d_in[w + 11];
    const float* Wrm    = (const float*)d_in[w + 12];
    const float* brm    = (const float*)d_in[w + 13];

    const size_t HH = 65536;  // 256*256

    // --- fold weights: W' = Wx @ Wlin ; bias' = (Σbl)@Wlin + blin ---
    for (int l = 0; l < 2; l++) {
        const float* wlin0 = Wlin + (size_t)(l * 3 + 0) * HH;
        const float* wlin1 = Wlin + (size_t)(l * 3 + 1) * HH;
        const float* wlin2 = Wlin + (size_t)(l * 3 + 2) * HH;
        float* WFl = WF + (size_t)l * 8 * HH;
        fold_w<<<256, 256>>>(Wl + (size_t)(l * 5 + 0) * HH, nullptr, nullptr, wlin0, WFl + 0 * HH);
        fold_w<<<256, 256>>>(Wl + (size_t)(l * 5 + 2) * HH, nullptr, nullptr, wlin0, WFl + 1 * HH);
        fold_w<<<256, 256>>>(Wl + (size_t)(l * 5 + 4) * HH, nullptr, nullptr, wlin0, WFl + 2 * HH);
        fold_w<<<256, 256>>>(Wr + (size_t)(l * 5 + 0) * HH,
                             Wr + (size_t)(l * 5 + 2) * HH,
                             Wr + (size_t)(l * 5 + 4) * HH, wlin0, WFl + 3 * HH);
        fold_w<<<256, 256>>>(Wl + (size_t)(l * 5 + 1) * HH, nullptr, nullptr, wlin1, WFl + 4 * HH);
        fold_w<<<256, 256>>>(Wr + (size_t)(l * 5 + 1) * HH, nullptr, nullptr, wlin1, WFl + 5 * HH);
        fold_w<<<256, 256>>>(Wl + (size_t)(l * 5 + 3) * HH, nullptr, nullptr, wlin2, WFl + 6 * HH);
        fold_w<<<256, 256>>>(Wr + (size_t)(l * 5 + 3) * HH, nullptr, nullptr, wlin2, WFl + 7 * HH);
        fold_b<<<1, 256>>>(bl + (l * 5 + 0) * 256, bl + (l * 5 + 2) * 256,
                           bl + (l * 5 + 4) * 256, wlin0, blin + (l * 3 + 0) * 256,
                           BF + l * 768 + 0);
        fold_b<<<1, 256>>>(bl + (l * 5 + 1) * 256, nullptr, nullptr, wlin1,
                           blin + (l * 3 + 1) * 256, BF + l * 768 + 256);
        fold_b<<<1, 256>>>(bl + (l * 5 + 3) * 256, nullptr, nullptr, wlin2,
                           blin + (l * 3 + 2) * 256, BF + l * 768 + 512);
    }

    // --- degree counts (indices are layer-invariant: compute once) ---
    cudaMemsetAsync(INV, 0, 720000 * sizeof(float), 0);
    int cblk = (EE + 255) / 256;
    count_k<<<cblk, 256>>>(dst_f,  INV + 0,      EE);
    count_k<<<cblk, 256>>>(dst_ra, INV + 200000, EE);
    count_k<<<cblk, 256>>>(dst_ta, INV + 400000, EE);
    count_k<<<cblk, 256>>>(dst_ar, INV + 600000, EE);
    count_k<<<cblk, 256>>>(dst_at, INV + 620000, EE);
    inv_k<<<(720000 + 255) / 256, 256>>>(INV, 720000);

    // --- input projections ---
    gemm256<<<(NACT  + 63) / 64, 256>>>(x_act,  Wp_act, nullptr, A, NACT,  64, 0);
    gemm256<<<(NRES  + 63) / 64, 256>>>(x_res,  Wp_res, nullptr, R, NRES,  32, 0);
    gemm256<<<(NTIME + 63) / 64, 256>>>(x_time, Wp_tim, nullptr, T, NTIME, 16, 0);

    // --- layers ---
    int sblk = (EE * 64) / 256;  // exact
    for (int l = 0; l < 2; l++) {
        cudaMemsetAsync(XA, 0, (size_t)NACT  * 1024 * sizeof(float), 0);
        cudaMemsetAsync(XR, 0, (size_t)NRES  * 512  * sizeof(float), 0);
        cudaMemsetAsync(XT, 0, (size_t)NTIME * 512  * sizeof(float), 0);

        scatter_k<<<sblk, 256>>>(src_f,  dst_f,  A, XA, 1024, 0,   EE);
        scatter_k<<<sblk, 256>>>(src_ra, dst_ra, R, XA, 1024, 256, EE);
        scatter_k<<<sblk, 256>>>(src_ta, dst_ta, T, XA, 1024, 512, EE);
        scatter_k<<<sblk, 256>>>(src_ar, dst_ar, A, XR, 512,  0,   EE);
        scatter_k<<<sblk, 256>>>(src_at, dst_at, A, XT, 512,  0,   EE);

        finalize_act_k<<<NACT, 256>>>(XA, A, INV, INV + 200000, INV + 400000);
        finalize2_k<<<NRES / 2, 256>>>(XR, R, INV + 600000, NRES);
        finalize2_k<<<NTIME / 2, 256>>>(XT, T, INV + 620000, NTIME);

        float* WFl = WF + (size_t)l * 8 * HH;
        gemm256<<<(NACT  + 63) / 64, 256>>>(XA, WFl + 0 * HH, BF + l * 768 + 0,   A, NACT,  1024, 1);
        gemm256<<<(NRES  + 63) / 64, 256>>>(XR, WFl + 4 * HH, BF + l * 768 + 256, R, NRES,  512,  1);
        gemm256<<<(NTIME + 63) / 64, 256>>>(XT, WFl + 6 * HH, BF + l * 768 + 512, T, NTIME, 512,  1);
    }

    // --- last-node pooling + heads ---
    cudaMemsetAsync(LAST, 0, GG * sizeof(int), 0);
    last_k<<<(NACT + 255) / 256, 256>>>(batch, LAST, NACT);
    heads_k<<<GG, 64>>>(A, LAST, Wo, bo, Wt, bt, Wrm, brm, (float*)d_out);
}